// round 1
// baseline (speedup 1.0000x reference)
#include <cuda_runtime.h>
#include <math.h>

// ---------------------------------------------------------------------------
// TransformerBlock (3x3 neighborhood attention), fp32 baseline.
// B=4, C=256, H=W=128, D=256 (==C), HID=1024. N_TOK = B*H*W = 65536.
// Token-major intermediate layout [N_TOK, C] so all GEMMs are row-major.
// ---------------------------------------------------------------------------

#define N_TOK 65536
#define CCH   256
#define HIDN  1024
#define HW    16384
#define WD    128
#define EPSF  1e-5f

// Scratch (static device globals: allocation APIs are forbidden)
__device__ float g_xc[(size_t)N_TOK * CCH];   // x transposed to [N,C]
__device__ float g_n1[(size_t)N_TOK * CCH];   // LN1(x)
__device__ float g_q [(size_t)N_TOK * CCH];
__device__ float g_k [(size_t)N_TOK * CCH];
__device__ float g_v [(size_t)N_TOK * CCH];
__device__ float g_x1[(size_t)N_TOK * CCH];   // xc + attn
__device__ float g_n2[(size_t)N_TOK * CCH];   // LN2(x1)
__device__ float g_h [(size_t)N_TOK * HIDN];  // gelu(fc1)
__device__ float g_y [(size_t)N_TOK * CCH];   // x1 + mlp (token-major)

// ---------------------------------------------------------------------------
// Kernel 1: LN1 over channels + transpose [B,C,H,W] -> token-major [N,C].
// Block = 256 threads handles 32 consecutive pixels of one image.
// ---------------------------------------------------------------------------
__global__ __launch_bounds__(256) void ln1_kernel(const float* __restrict__ x,
                                                  const float* __restrict__ gam,
                                                  const float* __restrict__ bet)
{
    __shared__ float s[256][33];
    __shared__ float mu[32], rs[32];
    int tid = threadIdx.x;
    int tx = tid & 31, ty = tid >> 5;          // tx = pixel lane, ty = warp
    int blk = blockIdx.x;
    int b  = blk >> 9;                         // 512 blocks per image
    int p0 = (blk & 511) << 5;                 // 32 pixels per block

    const float* xb = x + ((size_t)b * CCH) * HW + p0 + tx;
#pragma unroll
    for (int i = 0; i < 32; i++) {
        int c = ty * 32 + i;
        s[c][tx] = xb[(size_t)c * HW];         // coalesced across tx
    }
    __syncthreads();

    // stats: warp ty handles pixels ty*4 .. ty*4+3, 8 lanes per pixel
    {
        int px = ty * 4 + (tx >> 3);
        int j  = tx & 7;
        float s1 = 0.f, s2 = 0.f;
#pragma unroll
        for (int m = 0; m < 32; m++) {
            float vv = s[j + 8 * m][px];
            s1 += vv; s2 += vv * vv;
        }
#pragma unroll
        for (int off = 4; off >= 1; off >>= 1) {
            s1 += __shfl_xor_sync(0xffffffffu, s1, off);
            s2 += __shfl_xor_sync(0xffffffffu, s2, off);
        }
        if (j == 0) {
            float m1  = s1 * (1.f / 256.f);
            float var = fmaxf(s2 * (1.f / 256.f) - m1 * m1, 0.f);
            mu[px] = m1;
            rs[px] = rsqrtf(var + EPSF);
        }
    }
    __syncthreads();

    float gr = gam[tid], br = bet[tid];
    size_t tbase = ((size_t)b * HW + p0) * CCH + tid;
#pragma unroll
    for (int j = 0; j < 32; j++) {             // token p0+j, channel tid (coalesced)
        float xv = s[tid][j];
        g_xc[tbase + (size_t)j * CCH] = xv;
        g_n1[tbase + (size_t)j * CCH] = (xv - mu[j]) * rs[j] * gr + br;
    }
}

// ---------------------------------------------------------------------------
// SGEMM: C[M,N] = A[M,K] @ B[K,N] + bias, 128x128 tile, 8x8 per thread.
// epi: 0 = bias only; 1 = bias + exact GELU; 2 = bias + residual (res[M,N]).
// M is implicitly 65536 (gridDim.y * 128). N,K multiples of 128/8.
// ---------------------------------------------------------------------------
__global__ __launch_bounds__(256) void sgemm_kernel(
    const float* __restrict__ A, const float* __restrict__ B,
    const float* __restrict__ bias, const float* __restrict__ res,
    float* __restrict__ C, int N, int K, int epi)
{
    __shared__ float As[8][128];
    __shared__ float Bs[8][128];
    int tid = threadIdx.x;
    int tx = tid & 15, ty = tid >> 4;
    int bx = blockIdx.x, by = blockIdx.y;

    const float* Ab = A + (size_t)by * 128 * K;
    const float* Bb = B + bx * 128;

    int arow = tid >> 1,  ac4 = (tid & 1)  * 4;   // A: 128 rows x 8 cols
    int brow = tid >> 5,  bc4 = (tid & 31) * 4;   // B: 8 rows x 128 cols

    float acc[8][8];
#pragma unroll
    for (int i = 0; i < 8; i++)
#pragma unroll
        for (int j = 0; j < 8; j++) acc[i][j] = 0.f;

    for (int k0 = 0; k0 < K; k0 += 8) {
        float4 a4 = *(const float4*)(Ab + (size_t)arow * K + k0 + ac4);
        float4 b4 = *(const float4*)(Bb + (size_t)(k0 + brow) * N + bc4);
        As[ac4 + 0][arow] = a4.x; As[ac4 + 1][arow] = a4.y;
        As[ac4 + 2][arow] = a4.z; As[ac4 + 3][arow] = a4.w;
        *(float4*)&Bs[brow][bc4] = b4;
        __syncthreads();
#pragma unroll
        for (int k = 0; k < 8; k++) {
            float4 a0 = *(const float4*)&As[k][ty * 8];
            float4 a1 = *(const float4*)&As[k][ty * 8 + 4];
            float4 b0 = *(const float4*)&Bs[k][tx * 8];
            float4 b1 = *(const float4*)&Bs[k][tx * 8 + 4];
            float af[8] = {a0.x, a0.y, a0.z, a0.w, a1.x, a1.y, a1.z, a1.w};
            float bf[8] = {b0.x, b0.y, b0.z, b0.w, b1.x, b1.y, b1.z, b1.w};
#pragma unroll
            for (int i = 0; i < 8; i++)
#pragma unroll
                for (int j = 0; j < 8; j++) acc[i][j] += af[i] * bf[j];
        }
        __syncthreads();
    }

    int colBase = bx * 128 + tx * 8;
    float bb[8];
#pragma unroll
    for (int j = 0; j < 8; j++) bb[j] = bias[colBase + j];

#pragma unroll
    for (int i = 0; i < 8; i++) {
        size_t row = (size_t)by * 128 + ty * 8 + i;
        float o[8];
#pragma unroll
        for (int j = 0; j < 8; j++) {
            float vv = acc[i][j] + bb[j];
            if (epi == 1)
                vv = 0.5f * vv * (1.f + erff(vv * 0.70710678118654752f));
            o[j] = vv;
        }
        float* cp = C + row * N + colBase;
        if (epi == 2) {
            const float* rp = res + row * N + colBase;
            float4 r0 = *(const float4*)rp;
            float4 r1 = *(const float4*)(rp + 4);
            o[0] += r0.x; o[1] += r0.y; o[2] += r0.z; o[3] += r0.w;
            o[4] += r1.x; o[5] += r1.y; o[6] += r1.z; o[7] += r1.w;
        }
        *(float4*)cp       = make_float4(o[0], o[1], o[2], o[3]);
        *(float4*)(cp + 4) = make_float4(o[4], o[5], o[6], o[7]);
    }
}

// ---------------------------------------------------------------------------
// Kernel: 3x3 neighborhood attention + residual + fused LN2.
// One warp per token; D=256 -> 8 floats per lane.
// ---------------------------------------------------------------------------
__global__ __launch_bounds__(256) void attn_kernel(const float* __restrict__ g2,
                                                   const float* __restrict__ b2)
{
    int lane = threadIdx.x & 31;
    int warp = threadIdx.x >> 5;
    int t = blockIdx.x * 8 + warp;
    int p = t & (HW - 1);
    int yy = p >> 7, xx = p & 127;
    size_t base = (size_t)t * CCH + lane;

    float ql[8];
#pragma unroll
    for (int i = 0; i < 8; i++) ql[i] = g_q[base + 32 * i];

    float sc[9];
    int tns[9];
    unsigned vmask = 0;
#pragma unroll
    for (int n = 0; n < 9; n++) {
        int dy = n / 3 - 1, dx = n % 3 - 1;
        int ny = yy + dy, nx = xx + dx;
        bool valid = ((unsigned)ny < 128u) && ((unsigned)nx < 128u);
        int tn = t + dy * WD + dx;
        tns[n] = tn;
        if (valid) {
            vmask |= 1u << n;
            const float* kp = g_k + (size_t)tn * CCH + lane;
            float dot = 0.f;
#pragma unroll
            for (int i = 0; i < 8; i++) dot += ql[i] * kp[32 * i];
#pragma unroll
            for (int off = 16; off >= 1; off >>= 1)
                dot += __shfl_xor_sync(0xffffffffu, dot, off);
            sc[n] = dot * (1.0f / 16.0f);      // /sqrt(256)
        } else {
            sc[n] = -1e30f;
        }
    }

    float mx = sc[0];
#pragma unroll
    for (int n = 1; n < 9; n++) mx = fmaxf(mx, sc[n]);
    float w[9], wsum = 0.f;
#pragma unroll
    for (int n = 0; n < 9; n++) {
        w[n] = ((vmask >> n) & 1u) ? expf(sc[n] - mx) : 0.f;
        wsum += w[n];
    }
    float inv = 1.f / wsum;

    float acc[8];
#pragma unroll
    for (int i = 0; i < 8; i++) acc[i] = 0.f;
#pragma unroll
    for (int n = 0; n < 9; n++) {
        if ((vmask >> n) & 1u) {
            float wn = w[n] * inv;
            const float* vp = g_v + (size_t)tns[n] * CCH + lane;
#pragma unroll
            for (int i = 0; i < 8; i++) acc[i] += wn * vp[32 * i];
        }
    }

    // residual + LN2 (fused)
    float xv[8], s1 = 0.f, s2 = 0.f;
#pragma unroll
    for (int i = 0; i < 8; i++) {
        float val = g_xc[base + 32 * i] + acc[i];
        xv[i] = val; s1 += val; s2 += val * val;
    }
#pragma unroll
    for (int off = 16; off >= 1; off >>= 1) {
        s1 += __shfl_xor_sync(0xffffffffu, s1, off);
        s2 += __shfl_xor_sync(0xffffffffu, s2, off);
    }
    float m1  = s1 * (1.f / 256.f);
    float var = fmaxf(s2 * (1.f / 256.f) - m1 * m1, 0.f);
    float rstd = rsqrtf(var + EPSF);
#pragma unroll
    for (int i = 0; i < 8; i++) {
        int c = lane + 32 * i;
        g_x1[base + 32 * i] = xv[i];
        g_n2[base + 32 * i] = (xv[i] - m1) * rstd * g2[c] + b2[c];
    }
}

// ---------------------------------------------------------------------------
// Kernel: transpose token-major y [N,C] back to [B,C,H,W].
// ---------------------------------------------------------------------------
__global__ void out_transpose(float* __restrict__ out)
{
    __shared__ float tile[32][33];
    int tx = threadIdx.x, ty = threadIdx.y;    // (32, 8)
    int c0 = blockIdx.x * 32;
    int p0 = blockIdx.y * 32;
    int b  = blockIdx.z;

    size_t ybase = ((size_t)b * HW + p0) * CCH + c0;
#pragma unroll
    for (int j = 0; j < 4; j++) {
        int tok = ty + j * 8;
        tile[tok][tx] = g_y[ybase + (size_t)tok * CCH + tx];
    }
    __syncthreads();
    size_t obase = ((size_t)b * CCH + c0) * HW + p0;
#pragma unroll
    for (int j = 0; j < 4; j++) {
        int c = ty + j * 8;
        out[obase + (size_t)c * HW + tx] = tile[tx][c];
    }
}

// ---------------------------------------------------------------------------
extern "C" void kernel_launch(void* const* d_in, const int* in_sizes, int n_in,
                              void* d_out, int out_size)
{
    (void)in_sizes; (void)n_in; (void)out_size;
    const float* x     = (const float*)d_in[0];
    const float* wq    = (const float*)d_in[1];
    const float* bq    = (const float*)d_in[2];
    const float* wk    = (const float*)d_in[3];
    const float* bk    = (const float*)d_in[4];
    const float* wv    = (const float*)d_in[5];
    const float* bv    = (const float*)d_in[6];
    const float* ln1_g = (const float*)d_in[7];
    const float* ln1_b = (const float*)d_in[8];
    const float* ln2_g = (const float*)d_in[9];
    const float* ln2_b = (const float*)d_in[10];
    const float* fc1_w = (const float*)d_in[11];
    const float* fc1_b = (const float*)d_in[12];
    const float* fc2_w = (const float*)d_in[13];
    const float* fc2_b = (const float*)d_in[14];
    float* out = (float*)d_out;

    float *pn1, *pq, *pk, *pv, *pn2, *ph, *px1, *py;
    cudaGetSymbolAddress((void**)&pn1, g_n1);
    cudaGetSymbolAddress((void**)&pq,  g_q);
    cudaGetSymbolAddress((void**)&pk,  g_k);
    cudaGetSymbolAddress((void**)&pv,  g_v);
    cudaGetSymbolAddress((void**)&pn2, g_n2);
    cudaGetSymbolAddress((void**)&ph,  g_h);
    cudaGetSymbolAddress((void**)&px1, g_x1);
    cudaGetSymbolAddress((void**)&py,  g_y);

    // 1) LN1 + transpose
    ln1_kernel<<<2048, 256>>>(x, ln1_g, ln1_b);

    // 2-4) Q/K/V projections  (M=65536, N=256, K=256)
    dim3 gqkv(2, 512);
    sgemm_kernel<<<gqkv, 256>>>(pn1, wq, bq, nullptr, pq, 256, 256, 0);
    sgemm_kernel<<<gqkv, 256>>>(pn1, wk, bk, nullptr, pk, 256, 256, 0);
    sgemm_kernel<<<gqkv, 256>>>(pn1, wv, bv, nullptr, pv, 256, 256, 0);

    // 5) neighborhood attention + residual + LN2
    attn_kernel<<<8192, 256>>>(ln2_g, ln2_b);

    // 6) fc1 + GELU  (M=65536, N=1024, K=256)
    sgemm_kernel<<<dim3(8, 512), 256>>>(pn2, fc1_w, fc1_b, nullptr, ph, 1024, 256, 1);

    // 7) fc2 + bias + residual -> y  (M=65536, N=256, K=1024)
    sgemm_kernel<<<dim3(2, 512), 256>>>(ph, fc2_w, fc2_b, px1, py, 256, 1024, 2);

    // 8) transpose back to [B,C,H,W]
    out_transpose<<<dim3(8, 512, 4), dim3(32, 8)>>>(out);
}

// round 2
// speedup vs baseline: 2.1815x; 2.1815x over previous
#include <cuda_runtime.h>
#include <math.h>
#include <stdint.h>

// ---------------------------------------------------------------------------
// TransformerBlock (3x3 neighborhood attention).
// B=4, C=256, H=W=128, D=256, HID=1024. N_TOK = 65536.
// GEMMs on tensor cores via TF32 mma.sync (fp32 in/out, fp32 accum).
// ---------------------------------------------------------------------------

#define N_TOK 65536
#define CCH   256
#define HIDN  1024
#define HW    16384
#define WD    128
#define EPSF  1e-5f

__device__ float g_xc[(size_t)N_TOK * CCH];
__device__ float g_n1[(size_t)N_TOK * CCH];
__device__ float g_q [(size_t)N_TOK * CCH];
__device__ float g_k [(size_t)N_TOK * CCH];
__device__ float g_v [(size_t)N_TOK * CCH];
__device__ float g_x1[(size_t)N_TOK * CCH];
__device__ float g_n2[(size_t)N_TOK * CCH];
__device__ float g_h [(size_t)N_TOK * HIDN];
__device__ float g_y [(size_t)N_TOK * CCH];

// ---------------------------------------------------------------------------
// LN1 + transpose [B,C,H,W] -> [N,C]
// ---------------------------------------------------------------------------
__global__ __launch_bounds__(256) void ln1_kernel(const float* __restrict__ x,
                                                  const float* __restrict__ gam,
                                                  const float* __restrict__ bet)
{
    __shared__ float s[256][33];
    __shared__ float mu[32], rs[32];
    int tid = threadIdx.x;
    int tx = tid & 31, ty = tid >> 5;
    int blk = blockIdx.x;
    int b  = blk >> 9;
    int p0 = (blk & 511) << 5;

    const float* xb = x + ((size_t)b * CCH) * HW + p0 + tx;
#pragma unroll
    for (int i = 0; i < 32; i++) {
        int c = ty * 32 + i;
        s[c][tx] = xb[(size_t)c * HW];
    }
    __syncthreads();
    {
        int px = ty * 4 + (tx >> 3);
        int j  = tx & 7;
        float s1 = 0.f, s2 = 0.f;
#pragma unroll
        for (int m = 0; m < 32; m++) {
            float vv = s[j + 8 * m][px];
            s1 += vv; s2 += vv * vv;
        }
#pragma unroll
        for (int off = 4; off >= 1; off >>= 1) {
            s1 += __shfl_xor_sync(0xffffffffu, s1, off);
            s2 += __shfl_xor_sync(0xffffffffu, s2, off);
        }
        if (j == 0) {
            float m1  = s1 * (1.f / 256.f);
            float var = fmaxf(s2 * (1.f / 256.f) - m1 * m1, 0.f);
            mu[px] = m1;
            rs[px] = rsqrtf(var + EPSF);
        }
    }
    __syncthreads();

    float gr = gam[tid], br = bet[tid];
    size_t tbase = ((size_t)b * HW + p0) * CCH + tid;
#pragma unroll
    for (int j = 0; j < 32; j++) {
        float xv = s[tid][j];
        g_xc[tbase + (size_t)j * CCH] = xv;
        g_n1[tbase + (size_t)j * CCH] = (xv - mu[j]) * rs[j] * gr + br;
    }
}

// ---------------------------------------------------------------------------
// TF32 tensor-core GEMM: C[M,N] = A[M,K] @ B[K,N] + bias (+epi)
// 128x128x16 block tile, 8 warps (2x4), warp tile 64x32, m16n8k8 mma.
// epi: 0 = bias; 1 = bias + exact GELU; 2 = bias + residual.
// ---------------------------------------------------------------------------
__device__ __forceinline__ uint32_t f2tf(float f) {
    uint32_t u;
    asm("cvt.rna.tf32.f32 %0, %1;" : "=r"(u) : "f"(f));
    return u;
}
__device__ __forceinline__ void ldsm4(uint32_t& r0, uint32_t& r1, uint32_t& r2,
                                      uint32_t& r3, uint32_t addr) {
    asm volatile("ldmatrix.sync.aligned.m8n8.x4.shared.b16 {%0,%1,%2,%3}, [%4];"
                 : "=r"(r0), "=r"(r1), "=r"(r2), "=r"(r3) : "r"(addr));
}
__device__ __forceinline__ void mma_tf32(float* c, const uint32_t* a, const uint32_t* b) {
    asm volatile(
        "mma.sync.aligned.m16n8k8.row.col.f32.tf32.tf32.f32 "
        "{%0,%1,%2,%3},{%4,%5,%6,%7},{%8,%9},{%0,%1,%2,%3};"
        : "+f"(c[0]), "+f"(c[1]), "+f"(c[2]), "+f"(c[3])
        : "r"(a[0]), "r"(a[1]), "r"(a[2]), "r"(a[3]), "r"(b[0]), "r"(b[1]));
}

#define ASTRIDE 20   // fp32 words per smem row (80B, 16B-aligned, LDSM conflict-free)

__global__ __launch_bounds__(256) void tgemm_kernel(
    const float* __restrict__ A, const float* __restrict__ Bw,
    const float* __restrict__ bias, const float* __restrict__ res,
    float* __restrict__ C, int N, int K, int epi)
{
    __shared__ uint32_t As[128 * ASTRIDE];
    __shared__ uint32_t Bs[128 * ASTRIDE];   // n-major (transposed) B tile

    int tid = threadIdx.x;
    int bx = blockIdx.x, by = blockIdx.y;
    int lane = tid & 31, warp = tid >> 5;
    int wm = warp >> 2, wn = warp & 3;

    const float* Ag = A + (size_t)by * 128 * K;
    const float* Bg = Bw + (size_t)bx * 128;

    // global load indices (2 chunks each for A and B)
    int ar0 = tid >> 2,        ac0 = (tid & 3) * 4;
    int ar1 = (tid + 256) >> 2, ac1 = ((tid + 256) & 3) * 4;
    int bk0 = tid >> 5,        bn0 = (tid & 31) * 4;
    int bk1 = (tid + 256) >> 5, bn1 = ((tid + 256) & 31) * 4;

    uint32_t sAb = (uint32_t)__cvta_generic_to_shared(As);
    uint32_t sBb = (uint32_t)__cvta_generic_to_shared(Bs);

    // fragment smem addresses (byte)
    uint32_t aBase = sAb + 4 * (((wm * 64 + (lane & 15)) * ASTRIDE) + (lane >> 4) * 4);
    uint32_t bBase = sBb + 4 * (((wn * 32 + ((lane >> 4) & 1) * 8 + (lane & 7)) * ASTRIDE)
                                + ((lane >> 3) & 1) * 4);

    float acc[4][4][4];
#pragma unroll
    for (int i = 0; i < 4; i++)
#pragma unroll
        for (int j = 0; j < 4; j++)
#pragma unroll
            for (int k = 0; k < 4; k++) acc[i][j][k] = 0.f;

    float4 pa0, pa1, pb0, pb1;
    // prologue: load tile 0
    pa0 = *(const float4*)(Ag + (size_t)ar0 * K + ac0);
    pa1 = *(const float4*)(Ag + (size_t)ar1 * K + ac1);
    pb0 = *(const float4*)(Bg + (size_t)bk0 * N + bn0);
    pb1 = *(const float4*)(Bg + (size_t)bk1 * N + bn1);
    {
        uint4 u;
        u.x = f2tf(pa0.x); u.y = f2tf(pa0.y); u.z = f2tf(pa0.z); u.w = f2tf(pa0.w);
        *(uint4*)&As[ar0 * ASTRIDE + ac0] = u;
        u.x = f2tf(pa1.x); u.y = f2tf(pa1.y); u.z = f2tf(pa1.z); u.w = f2tf(pa1.w);
        *(uint4*)&As[ar1 * ASTRIDE + ac1] = u;
        Bs[(bn0 + 0) * ASTRIDE + bk0] = f2tf(pb0.x);
        Bs[(bn0 + 1) * ASTRIDE + bk0] = f2tf(pb0.y);
        Bs[(bn0 + 2) * ASTRIDE + bk0] = f2tf(pb0.z);
        Bs[(bn0 + 3) * ASTRIDE + bk0] = f2tf(pb0.w);
        Bs[(bn1 + 0) * ASTRIDE + bk1] = f2tf(pb1.x);
        Bs[(bn1 + 1) * ASTRIDE + bk1] = f2tf(pb1.y);
        Bs[(bn1 + 2) * ASTRIDE + bk1] = f2tf(pb1.z);
        Bs[(bn1 + 3) * ASTRIDE + bk1] = f2tf(pb1.w);
    }
    __syncthreads();

    int niter = K >> 4;
    for (int it = 0; it < niter; ++it) {
        bool more = (it + 1) < niter;
        if (more) {
            int k0 = (it + 1) << 4;
            pa0 = *(const float4*)(Ag + (size_t)ar0 * K + k0 + ac0);
            pa1 = *(const float4*)(Ag + (size_t)ar1 * K + k0 + ac1);
            pb0 = *(const float4*)(Bg + (size_t)(k0 + bk0) * N + bn0);
            pb1 = *(const float4*)(Bg + (size_t)(k0 + bk1) * N + bn1);
        }
        // compute 2 k-steps of 8
#pragma unroll
        for (int s = 0; s < 2; s++) {
            uint32_t a[4][4], b[4][2];
#pragma unroll
            for (int mi = 0; mi < 4; mi++)
                ldsm4(a[mi][0], a[mi][1], a[mi][2], a[mi][3],
                      aBase + mi * (16 * ASTRIDE * 4) + s * 32);
#pragma unroll
            for (int h = 0; h < 2; h++) {
                uint32_t r0, r1, r2, r3;
                ldsm4(r0, r1, r2, r3, bBase + h * (16 * ASTRIDE * 4) + s * 32);
                b[h * 2][0] = r0; b[h * 2][1] = r1;
                b[h * 2 + 1][0] = r2; b[h * 2 + 1][1] = r3;
            }
#pragma unroll
            for (int mi = 0; mi < 4; mi++)
#pragma unroll
                for (int ni = 0; ni < 4; ni++)
                    mma_tf32(acc[mi][ni], a[mi], b[ni]);
        }
        __syncthreads();
        if (more) {
            uint4 u;
            u.x = f2tf(pa0.x); u.y = f2tf(pa0.y); u.z = f2tf(pa0.z); u.w = f2tf(pa0.w);
            *(uint4*)&As[ar0 * ASTRIDE + ac0] = u;
            u.x = f2tf(pa1.x); u.y = f2tf(pa1.y); u.z = f2tf(pa1.z); u.w = f2tf(pa1.w);
            *(uint4*)&As[ar1 * ASTRIDE + ac1] = u;
            Bs[(bn0 + 0) * ASTRIDE + bk0] = f2tf(pb0.x);
            Bs[(bn0 + 1) * ASTRIDE + bk0] = f2tf(pb0.y);
            Bs[(bn0 + 2) * ASTRIDE + bk0] = f2tf(pb0.z);
            Bs[(bn0 + 3) * ASTRIDE + bk0] = f2tf(pb0.w);
            Bs[(bn1 + 0) * ASTRIDE + bk1] = f2tf(pb1.x);
            Bs[(bn1 + 1) * ASTRIDE + bk1] = f2tf(pb1.y);
            Bs[(bn1 + 2) * ASTRIDE + bk1] = f2tf(pb1.z);
            Bs[(bn1 + 3) * ASTRIDE + bk1] = f2tf(pb1.w);
            __syncthreads();
        }
    }

    // epilogue
    int colBase = bx * 128 + wn * 32;
    int rowBase = by * 128 + wm * 64 + (lane >> 2);
#pragma unroll
    for (int ni = 0; ni < 4; ni++) {
        int c = colBase + ni * 8 + (lane & 3) * 2;
        float bi0 = bias[c], bi1 = bias[c + 1];
#pragma unroll
        for (int mi = 0; mi < 4; mi++) {
            int r0 = rowBase + mi * 16;
            float v00 = acc[mi][ni][0] + bi0;
            float v01 = acc[mi][ni][1] + bi1;
            float v10 = acc[mi][ni][2] + bi0;
            float v11 = acc[mi][ni][3] + bi1;
            if (epi == 1) {
                v00 = 0.5f * v00 * (1.f + erff(v00 * 0.70710678118654752f));
                v01 = 0.5f * v01 * (1.f + erff(v01 * 0.70710678118654752f));
                v10 = 0.5f * v10 * (1.f + erff(v10 * 0.70710678118654752f));
                v11 = 0.5f * v11 * (1.f + erff(v11 * 0.70710678118654752f));
            }
            if (epi == 2) {
                float2 r = *(const float2*)(res + (size_t)r0 * N + c);
                float2 r2v = *(const float2*)(res + (size_t)(r0 + 8) * N + c);
                v00 += r.x; v01 += r.y; v10 += r2v.x; v11 += r2v.y;
            }
            *(float2*)(C + (size_t)r0 * N + c) = make_float2(v00, v01);
            *(float2*)(C + (size_t)(r0 + 8) * N + c) = make_float2(v10, v11);
        }
    }
}

// ---------------------------------------------------------------------------
// 3x3 neighborhood attention + residual + fused LN2
// ---------------------------------------------------------------------------
__global__ __launch_bounds__(256) void attn_kernel(const float* __restrict__ g2,
                                                   const float* __restrict__ b2)
{
    int lane = threadIdx.x & 31;
    int warp = threadIdx.x >> 5;
    int t = blockIdx.x * 8 + warp;
    int p = t & (HW - 1);
    int yy = p >> 7, xx = p & 127;
    size_t base = (size_t)t * CCH + lane;

    float ql[8];
#pragma unroll
    for (int i = 0; i < 8; i++) ql[i] = g_q[base + 32 * i];

    float sc[9];
    int tns[9];
    unsigned vmask = 0;
#pragma unroll
    for (int n = 0; n < 9; n++) {
        int dy = n / 3 - 1, dx = n % 3 - 1;
        int ny = yy + dy, nx = xx + dx;
        bool valid = ((unsigned)ny < 128u) && ((unsigned)nx < 128u);
        int tn = t + dy * WD + dx;
        tns[n] = tn;
        if (valid) {
            vmask |= 1u << n;
            const float* kp = g_k + (size_t)tn * CCH + lane;
            float dot = 0.f;
#pragma unroll
            for (int i = 0; i < 8; i++) dot += ql[i] * kp[32 * i];
#pragma unroll
            for (int off = 16; off >= 1; off >>= 1)
                dot += __shfl_xor_sync(0xffffffffu, dot, off);
            sc[n] = dot * (1.0f / 16.0f);
        } else {
            sc[n] = -1e30f;
        }
    }

    float mx = sc[0];
#pragma unroll
    for (int n = 1; n < 9; n++) mx = fmaxf(mx, sc[n]);
    float w[9], wsum = 0.f;
#pragma unroll
    for (int n = 0; n < 9; n++) {
        w[n] = ((vmask >> n) & 1u) ? expf(sc[n] - mx) : 0.f;
        wsum += w[n];
    }
    float inv = 1.f / wsum;

    float acc[8];
#pragma unroll
    for (int i = 0; i < 8; i++) acc[i] = 0.f;
#pragma unroll
    for (int n = 0; n < 9; n++) {
        if ((vmask >> n) & 1u) {
            float wn = w[n] * inv;
            const float* vp = g_v + (size_t)tns[n] * CCH + lane;
#pragma unroll
            for (int i = 0; i < 8; i++) acc[i] += wn * vp[32 * i];
        }
    }

    float xv[8], s1 = 0.f, s2 = 0.f;
#pragma unroll
    for (int i = 0; i < 8; i++) {
        float val = g_xc[base + 32 * i] + acc[i];
        xv[i] = val; s1 += val; s2 += val * val;
    }
#pragma unroll
    for (int off = 16; off >= 1; off >>= 1) {
        s1 += __shfl_xor_sync(0xffffffffu, s1, off);
        s2 += __shfl_xor_sync(0xffffffffu, s2, off);
    }
    float m1  = s1 * (1.f / 256.f);
    float var = fmaxf(s2 * (1.f / 256.f) - m1 * m1, 0.f);
    float rstd = rsqrtf(var + EPSF);
#pragma unroll
    for (int i = 0; i < 8; i++) {
        int c = lane + 32 * i;
        g_x1[base + 32 * i] = xv[i];
        g_n2[base + 32 * i] = (xv[i] - m1) * rstd * g2[c] + b2[c];
    }
}

// ---------------------------------------------------------------------------
// transpose [N,C] -> [B,C,H,W]
// ---------------------------------------------------------------------------
__global__ void out_transpose(float* __restrict__ out)
{
    __shared__ float tile[32][33];
    int tx = threadIdx.x, ty = threadIdx.y;
    int c0 = blockIdx.x * 32;
    int p0 = blockIdx.y * 32;
    int b  = blockIdx.z;

    size_t ybase = ((size_t)b * HW + p0) * CCH + c0;
#pragma unroll
    for (int j = 0; j < 4; j++) {
        int tok = ty + j * 8;
        tile[tok][tx] = g_y[ybase + (size_t)tok * CCH + tx];
    }
    __syncthreads();
    size_t obase = ((size_t)b * CCH + c0) * HW + p0;
#pragma unroll
    for (int j = 0; j < 4; j++) {
        int c = ty + j * 8;
        out[obase + (size_t)c * HW + tx] = tile[tx][c];
    }
}

// ---------------------------------------------------------------------------
extern "C" void kernel_launch(void* const* d_in, const int* in_sizes, int n_in,
                              void* d_out, int out_size)
{
    (void)in_sizes; (void)n_in; (void)out_size;
    const float* x     = (const float*)d_in[0];
    const float* wq    = (const float*)d_in[1];
    const float* bq    = (const float*)d_in[2];
    const float* wk    = (const float*)d_in[3];
    const float* bk    = (const float*)d_in[4];
    const float* wv    = (const float*)d_in[5];
    const float* bv    = (const float*)d_in[6];
    const float* ln1_g = (const float*)d_in[7];
    const float* ln1_b = (const float*)d_in[8];
    const float* ln2_g = (const float*)d_in[9];
    const float* ln2_b = (const float*)d_in[10];
    const float* fc1_w = (const float*)d_in[11];
    const float* fc1_b = (const float*)d_in[12];
    const float* fc2_w = (const float*)d_in[13];
    const float* fc2_b = (const float*)d_in[14];
    float* out = (float*)d_out;

    float *pn1, *pq, *pk, *pv, *pn2, *ph, *px1, *py;
    cudaGetSymbolAddress((void**)&pn1, g_n1);
    cudaGetSymbolAddress((void**)&pq,  g_q);
    cudaGetSymbolAddress((void**)&pk,  g_k);
    cudaGetSymbolAddress((void**)&pv,  g_v);
    cudaGetSymbolAddress((void**)&pn2, g_n2);
    cudaGetSymbolAddress((void**)&ph,  g_h);
    cudaGetSymbolAddress((void**)&px1, g_x1);
    cudaGetSymbolAddress((void**)&py,  g_y);

    ln1_kernel<<<2048, 256>>>(x, ln1_g, ln1_b);

    dim3 gqkv(2, 512);
    tgemm_kernel<<<gqkv, 256>>>(pn1, wq, bq, nullptr, pq, 256, 256, 0);
    tgemm_kernel<<<gqkv, 256>>>(pn1, wk, bk, nullptr, pk, 256, 256, 0);
    tgemm_kernel<<<gqkv, 256>>>(pn1, wv, bv, nullptr, pv, 256, 256, 0);

    attn_kernel<<<8192, 256>>>(ln2_g, ln2_b);

    tgemm_kernel<<<dim3(8, 512), 256>>>(pn2, fc1_w, fc1_b, nullptr, ph, 1024, 256, 1);
    tgemm_kernel<<<dim3(2, 512), 256>>>(ph, fc2_w, fc2_b, px1, py, 256, 1024, 2);

    out_transpose<<<dim3(8, 512, 4), dim3(32, 8)>>>(out);
}

// round 4
// speedup vs baseline: 3.6232x; 1.6609x over previous
#include <cuda_runtime.h>
#include <math.h>
#include <stdint.h>

// ---------------------------------------------------------------------------
// TransformerBlock (3x3 neighborhood attention). TF32 mma.sync GEMMs with
// pre-converted tf32 operands + cp.async 3-stage pipeline.
// ---------------------------------------------------------------------------

#define N_TOK 65536
#define CCH   256
#define HIDN  1024
#define HW    16384
#define WD    128
#define EPSF  1e-5f

__device__ float g_xc[(size_t)N_TOK * CCH];
__device__ float g_n1[(size_t)N_TOK * CCH];   // tf32-rounded
__device__ float g_q [(size_t)N_TOK * CCH];
__device__ float g_k [(size_t)N_TOK * CCH];
__device__ float g_v [(size_t)N_TOK * CCH];
__device__ float g_x1[(size_t)N_TOK * CCH];
__device__ float g_n2[(size_t)N_TOK * CCH];   // tf32-rounded
__device__ float g_h [(size_t)N_TOK * HIDN];  // tf32-rounded
__device__ float g_y [(size_t)N_TOK * CCH];

// transposed tf32 weights: wt[n][k]
__device__ float g_wq_t[CCH * CCH];
__device__ float g_wk_t[CCH * CCH];
__device__ float g_wv_t[CCH * CCH];
__device__ float g_w1_t[(size_t)CCH * HIDN];
__device__ float g_w2_t[(size_t)CCH * HIDN];

__device__ __forceinline__ uint32_t f2tf(float f) {
    uint32_t u;
    asm("cvt.rna.tf32.f32 %0, %1;" : "=r"(u) : "f"(f));
    return u;
}
__device__ __forceinline__ float f2tff(float f) {
    return __uint_as_float(f2tf(f));
}

// ---------------------------------------------------------------------------
// weight transpose + tf32 round: w[K][N] -> wt[N][K]
// ---------------------------------------------------------------------------
__global__ void wconv_kernel(const float* __restrict__ w, float* __restrict__ wt,
                             int K, int N)
{
    __shared__ float t[32][33];
    int tx = threadIdx.x, ty = threadIdx.y;    // (32,8)
    int n0 = blockIdx.x * 32, k0 = blockIdx.y * 32;
#pragma unroll
    for (int j = 0; j < 4; j++)
        t[ty + j * 8][tx] = w[(size_t)(k0 + ty + j * 8) * N + n0 + tx];
    __syncthreads();
#pragma unroll
    for (int j = 0; j < 4; j++)
        wt[(size_t)(n0 + ty + j * 8) * K + k0 + tx] = f2tff(t[tx][ty + j * 8]);
}

// ---------------------------------------------------------------------------
// LN1 + transpose [B,C,H,W] -> [N,C]; n1 stored tf32-rounded
// ---------------------------------------------------------------------------
__global__ __launch_bounds__(256) void ln1_kernel(const float* __restrict__ x,
                                                  const float* __restrict__ gam,
                                                  const float* __restrict__ bet)
{
    __shared__ float s[256][33];
    __shared__ float mu[32], rs[32];
    int tid = threadIdx.x;
    int tx = tid & 31, ty = tid >> 5;
    int blk = blockIdx.x;
    int b  = blk >> 9;
    int p0 = (blk & 511) << 5;

    const float* xb = x + ((size_t)b * CCH) * HW + p0 + tx;
#pragma unroll
    for (int i = 0; i < 32; i++) {
        int c = ty * 32 + i;
        s[c][tx] = xb[(size_t)c * HW];
    }
    __syncthreads();
    {
        int px = ty * 4 + (tx >> 3);
        int j  = tx & 7;
        float s1 = 0.f, s2 = 0.f;
#pragma unroll
        for (int m = 0; m < 32; m++) {
            float vv = s[j + 8 * m][px];
            s1 += vv; s2 += vv * vv;
        }
#pragma unroll
        for (int off = 4; off >= 1; off >>= 1) {
            s1 += __shfl_xor_sync(0xffffffffu, s1, off);
            s2 += __shfl_xor_sync(0xffffffffu, s2, off);
        }
        if (j == 0) {
            float m1  = s1 * (1.f / 256.f);
            float var = fmaxf(s2 * (1.f / 256.f) - m1 * m1, 0.f);
            mu[px] = m1;
            rs[px] = rsqrtf(var + EPSF);
        }
    }
    __syncthreads();

    float gr = gam[tid], br = bet[tid];
    size_t tbase = ((size_t)b * HW + p0) * CCH + tid;
#pragma unroll
    for (int j = 0; j < 32; j++) {
        float xv = s[tid][j];
        g_xc[tbase + (size_t)j * CCH] = xv;
        g_n1[tbase + (size_t)j * CCH] = f2tff((xv - mu[j]) * rs[j] * gr + br);
    }
}

// ---------------------------------------------------------------------------
// TF32 GEMM, operands pre-converted. A row-major [M][K], Bt n-major [N][K].
// 128x128x16 tile, 8 warps (warp tile 64x32), 3-stage cp.async pipeline.
// epi: 0 bias; 1 bias+GELU (output tf32-rounded); 2 bias+residual.
// ---------------------------------------------------------------------------
#define ASTR 20
#define ABYTES (128 * ASTR * 4)            // 10240
#define STAGE_BYTES (2 * ABYTES)           // A + B per stage
#define NSTAGE 3
#define SMEM_TOTAL (NSTAGE * STAGE_BYTES)  // 61440

__device__ __forceinline__ void cpasync16(uint32_t dst, const float* src) {
    asm volatile("cp.async.cg.shared.global [%0], [%1], 16;" :: "r"(dst), "l"(src));
}
__device__ __forceinline__ void ldsm4(uint32_t& r0, uint32_t& r1, uint32_t& r2,
                                      uint32_t& r3, uint32_t addr) {
    asm volatile("ldmatrix.sync.aligned.m8n8.x4.shared.b16 {%0,%1,%2,%3}, [%4];"
                 : "=r"(r0), "=r"(r1), "=r"(r2), "=r"(r3) : "r"(addr));
}
__device__ __forceinline__ void mma_tf32(float* c, const uint32_t* a, const uint32_t* b) {
    asm volatile(
        "mma.sync.aligned.m16n8k8.row.col.f32.tf32.tf32.f32 "
        "{%0,%1,%2,%3},{%4,%5,%6,%7},{%8,%9},{%0,%1,%2,%3};"
        : "+f"(c[0]), "+f"(c[1]), "+f"(c[2]), "+f"(c[3])
        : "r"(a[0]), "r"(a[1]), "r"(a[2]), "r"(a[3]), "r"(b[0]), "r"(b[1]));
}

__global__ __launch_bounds__(256) void tgemm_kernel(
    const float* __restrict__ A, const float* __restrict__ Bt,
    const float* __restrict__ bias, const float* __restrict__ res,
    float* __restrict__ C, int N, int K, int epi)
{
    extern __shared__ uint32_t smem[];
    int tid = threadIdx.x;
    int bx = blockIdx.x, by = blockIdx.y;
    int lane = tid & 31, warp = tid >> 5;
    int wm = warp >> 2, wn = warp & 3;

    const float* Ag  = A  + (size_t)by * 128 * K;
    const float* Btg = Bt + (size_t)bx * 128 * K;

    int r0 = tid >> 2, c0 = (tid & 3) * 4;   // 64 rows x 16 cols per 256 threads

    uint32_t sBase = (uint32_t)__cvta_generic_to_shared(smem);
    const float* Asrc = Ag  + (size_t)r0 * K + c0;
    const float* Bsrc = Btg + (size_t)r0 * K + c0;
    uint32_t dA0 = sBase + (r0 * ASTR + c0) * 4;
    uint32_t dA1 = sBase + ((r0 + 64) * ASTR + c0) * 4;

    uint32_t aOff = 4 * (((wm * 64 + (lane & 15)) * ASTR) + (lane >> 4) * 4);
    uint32_t bOff = ABYTES + 4 * (((wn * 32 + ((lane >> 4) & 1) * 8 + (lane & 7)) * ASTR)
                                  + ((lane >> 3) & 1) * 4);

    float acc[4][4][4];
#pragma unroll
    for (int i = 0; i < 4; i++)
#pragma unroll
        for (int j = 0; j < 4; j++)
#pragma unroll
            for (int k = 0; k < 4; k++) acc[i][j][k] = 0.f;

    int niter = K >> 4;

    // prologue: stages 0,1
#pragma unroll
    for (int p = 0; p < 2; p++) {
        uint32_t sb = p * STAGE_BYTES;
        int k0 = p << 4;
        cpasync16(dA0 + sb, Asrc + k0);
        cpasync16(dA1 + sb, Asrc + (size_t)64 * K + k0);
        cpasync16(dA0 + sb + ABYTES, Bsrc + k0);
        cpasync16(dA1 + sb + ABYTES, Bsrc + (size_t)64 * K + k0);
        asm volatile("cp.async.commit_group;");
    }

    int st = 0;
    for (int it = 0; it < niter; ++it) {
        int pre = it + 2;
        if (pre < niter) {
            int ps = pre % NSTAGE;
            uint32_t sb = ps * STAGE_BYTES;
            int k0 = pre << 4;
            cpasync16(dA0 + sb, Asrc + k0);
            cpasync16(dA1 + sb, Asrc + (size_t)64 * K + k0);
            cpasync16(dA0 + sb + ABYTES, Bsrc + k0);
            cpasync16(dA1 + sb + ABYTES, Bsrc + (size_t)64 * K + k0);
        }
        asm volatile("cp.async.commit_group;");
        asm volatile("cp.async.wait_group 2;" ::: "memory");
        __syncthreads();

        uint32_t stb = sBase + st * STAGE_BYTES;
#pragma unroll
        for (int s = 0; s < 2; s++) {
            uint32_t a[4][4], b[4][2];
#pragma unroll
            for (int mi = 0; mi < 4; mi++)
                ldsm4(a[mi][0], a[mi][1], a[mi][2], a[mi][3],
                      stb + aOff + mi * (16 * ASTR * 4) + s * 32);
#pragma unroll
            for (int h = 0; h < 2; h++) {
                uint32_t q0, q1, q2, q3;
                ldsm4(q0, q1, q2, q3, stb + bOff + h * (16 * ASTR * 4) + s * 32);
                b[h * 2][0] = q0; b[h * 2][1] = q1;
                b[h * 2 + 1][0] = q2; b[h * 2 + 1][1] = q3;
            }
#pragma unroll
            for (int mi = 0; mi < 4; mi++)
#pragma unroll
                for (int ni = 0; ni < 4; ni++)
                    mma_tf32(acc[mi][ni], a[mi], b[ni]);
        }
        __syncthreads();
        st = (st + 1) % NSTAGE;
    }

    // epilogue
    int colBase = bx * 128 + wn * 32;
    int rowBase = by * 128 + wm * 64 + (lane >> 2);
#pragma unroll
    for (int ni = 0; ni < 4; ni++) {
        int c = colBase + ni * 8 + (lane & 3) * 2;
        float bi0 = bias[c], bi1 = bias[c + 1];
#pragma unroll
        for (int mi = 0; mi < 4; mi++) {
            int rr = rowBase + mi * 16;
            float v00 = acc[mi][ni][0] + bi0;
            float v01 = acc[mi][ni][1] + bi1;
            float v10 = acc[mi][ni][2] + bi0;
            float v11 = acc[mi][ni][3] + bi1;
            if (epi == 1) {
                v00 = f2tff(0.5f * v00 * (1.f + erff(v00 * 0.70710678118654752f)));
                v01 = f2tff(0.5f * v01 * (1.f + erff(v01 * 0.70710678118654752f)));
                v10 = f2tff(0.5f * v10 * (1.f + erff(v10 * 0.70710678118654752f)));
                v11 = f2tff(0.5f * v11 * (1.f + erff(v11 * 0.70710678118654752f)));
            }
            if (epi == 2) {
                float2 r  = *(const float2*)(res + (size_t)rr * N + c);
                float2 r2 = *(const float2*)(res + (size_t)(rr + 8) * N + c);
                v00 += r.x; v01 += r.y; v10 += r2.x; v11 += r2.y;
            }
            *(float2*)(C + (size_t)rr * N + c) = make_float2(v00, v01);
            *(float2*)(C + (size_t)(rr + 8) * N + c) = make_float2(v10, v11);
        }
    }
}

// ---------------------------------------------------------------------------
// 3x3 neighborhood attention + residual + fused LN2 (n2 tf32-rounded)
// ---------------------------------------------------------------------------
__global__ __launch_bounds__(256) void attn_kernel(const float* __restrict__ g2,
                                                   const float* __restrict__ b2)
{
    int lane = threadIdx.x & 31;
    int warp = threadIdx.x >> 5;
    int t = blockIdx.x * 8 + warp;
    int p = t & (HW - 1);
    int yy = p >> 7, xx = p & 127;
    size_t base = (size_t)t * CCH + lane;

    float ql[8];
#pragma unroll
    for (int i = 0; i < 8; i++) ql[i] = g_q[base + 32 * i];

    float sc[9];
    int tns[9];
    unsigned vmask = 0;
#pragma unroll
    for (int n = 0; n < 9; n++) {
        int dy = n / 3 - 1, dx = n % 3 - 1;
        int ny = yy + dy, nx = xx + dx;
        bool valid = ((unsigned)ny < 128u) && ((unsigned)nx < 128u);
        int tn = t + dy * WD + dx;
        tns[n] = tn;
        if (valid) {
            vmask |= 1u << n;
            const float* kp = g_k + (size_t)tn * CCH + lane;
            float dot = 0.f;
#pragma unroll
            for (int i = 0; i < 8; i++) dot += ql[i] * kp[32 * i];
#pragma unroll
            for (int off = 16; off >= 1; off >>= 1)
                dot += __shfl_xor_sync(0xffffffffu, dot, off);
            sc[n] = dot * (1.0f / 16.0f);
        } else {
            sc[n] = -1e30f;
        }
    }

    float mx = sc[0];
#pragma unroll
    for (int n = 1; n < 9; n++) mx = fmaxf(mx, sc[n]);
    float w[9], wsum = 0.f;
#pragma unroll
    for (int n = 0; n < 9; n++) {
        w[n] = ((vmask >> n) & 1u) ? expf(sc[n] - mx) : 0.f;
        wsum += w[n];
    }
    float inv = 1.f / wsum;

    float acc[8];
#pragma unroll
    for (int i = 0; i < 8; i++) acc[i] = 0.f;
#pragma unroll
    for (int n = 0; n < 9; n++) {
        if ((vmask >> n) & 1u) {
            float wn = w[n] * inv;
            const float* vp = g_v + (size_t)tns[n] * CCH + lane;
#pragma unroll
            for (int i = 0; i < 8; i++) acc[i] += wn * vp[32 * i];
        }
    }

    float xv[8], s1 = 0.f, s2 = 0.f;
#pragma unroll
    for (int i = 0; i < 8; i++) {
        float val = g_xc[base + 32 * i] + acc[i];
        xv[i] = val; s1 += val; s2 += val * val;
    }
#pragma unroll
    for (int off = 16; off >= 1; off >>= 1) {
        s1 += __shfl_xor_sync(0xffffffffu, s1, off);
        s2 += __shfl_xor_sync(0xffffffffu, s2, off);
    }
    float m1  = s1 * (1.f / 256.f);
    float var = fmaxf(s2 * (1.f / 256.f) - m1 * m1, 0.f);
    float rstd = rsqrtf(var + EPSF);
#pragma unroll
    for (int i = 0; i < 8; i++) {
        int c = lane + 32 * i;
        g_x1[base + 32 * i] = xv[i];
        g_n2[base + 32 * i] = f2tff((xv[i] - m1) * rstd * g2[c] + b2[c]);
    }
}

// ---------------------------------------------------------------------------
// transpose [N,C] -> [B,C,H,W]
// ---------------------------------------------------------------------------
__global__ void out_transpose(float* __restrict__ out)
{
    __shared__ float tile[32][33];
    int tx = threadIdx.x, ty = threadIdx.y;
    int c0 = blockIdx.x * 32;
    int p0 = blockIdx.y * 32;
    int b  = blockIdx.z;

    size_t ybase = ((size_t)b * HW + p0) * CCH + c0;
#pragma unroll
    for (int j = 0; j < 4; j++) {
        int tok = ty + j * 8;
        tile[tok][tx] = g_y[ybase + (size_t)tok * CCH + tx];
    }
    __syncthreads();
    size_t obase = ((size_t)b * CCH + c0) * HW + p0;
#pragma unroll
    for (int j = 0; j < 4; j++) {
        int c = ty + j * 8;
        out[obase + (size_t)c * HW + tx] = tile[tx][c];
    }
}

// ---------------------------------------------------------------------------
extern "C" void kernel_launch(void* const* d_in, const int* in_sizes, int n_in,
                              void* d_out, int out_size)
{
    (void)in_sizes; (void)n_in; (void)out_size;
    const float* x     = (const float*)d_in[0];
    const float* wq    = (const float*)d_in[1];
    const float* bq    = (const float*)d_in[2];
    const float* wk    = (const float*)d_in[3];
    const float* bk    = (const float*)d_in[4];
    const float* wv    = (const float*)d_in[5];
    const float* bv    = (const float*)d_in[6];
    const float* ln1_g = (const float*)d_in[7];
    const float* ln1_b = (const float*)d_in[8];
    const float* ln2_g = (const float*)d_in[9];
    const float* ln2_b = (const float*)d_in[10];
    const float* fc1_w = (const float*)d_in[11];
    const float* fc1_b = (const float*)d_in[12];
    const float* fc2_w = (const float*)d_in[13];
    const float* fc2_b = (const float*)d_in[14];
    float* out = (float*)d_out;

    float *pn1, *pq, *pk, *pv, *pn2, *ph, *px1, *py;
    float *pwq, *pwk, *pwv, *pw1, *pw2;
    cudaGetSymbolAddress((void**)&pn1, g_n1);
    cudaGetSymbolAddress((void**)&pq,  g_q);
    cudaGetSymbolAddress((void**)&pk,  g_k);
    cudaGetSymbolAddress((void**)&pv,  g_v);
    cudaGetSymbolAddress((void**)&pn2, g_n2);
    cudaGetSymbolAddress((void**)&ph,  g_h);
    cudaGetSymbolAddress((void**)&px1, g_x1);
    cudaGetSymbolAddress((void**)&py,  g_y);
    cudaGetSymbolAddress((void**)&pwq, g_wq_t);
    cudaGetSymbolAddress((void**)&pwk, g_wk_t);
    cudaGetSymbolAddress((void**)&pwv, g_wv_t);
    cudaGetSymbolAddress((void**)&pw1, g_w1_t);
    cudaGetSymbolAddress((void**)&pw2, g_w2_t);

    // Unconditional (idempotent, deterministic, not a stream op — capture-safe).
    cudaFuncSetAttribute(tgemm_kernel,
                         cudaFuncAttributeMaxDynamicSharedMemorySize, SMEM_TOTAL);

    dim3 tb(32, 8);
    wconv_kernel<<<dim3(8, 8),  tb>>>(wq,    pwq, 256, 256);
    wconv_kernel<<<dim3(8, 8),  tb>>>(wk,    pwk, 256, 256);
    wconv_kernel<<<dim3(8, 8),  tb>>>(wv,    pwv, 256, 256);
    wconv_kernel<<<dim3(32, 8), tb>>>(fc1_w, pw1, 256, 1024);
    wconv_kernel<<<dim3(8, 32), tb>>>(fc2_w, pw2, 1024, 256);

    ln1_kernel<<<2048, 256>>>(x, ln1_g, ln1_b);

    dim3 gqkv(2, 512);
    tgemm_kernel<<<gqkv, 256, SMEM_TOTAL>>>(pn1, pwq, bq, nullptr, pq, 256, 256, 0);
    tgemm_kernel<<<gqkv, 256, SMEM_TOTAL>>>(pn1, pwk, bk, nullptr, pk, 256, 256, 0);
    tgemm_kernel<<<gqkv, 256, SMEM_TOTAL>>>(pn1, pwv, bv, nullptr, pv, 256, 256, 0);

    attn_kernel<<<8192, 256>>>(ln2_g, ln2_b);

    tgemm_kernel<<<dim3(8, 512), 256, SMEM_TOTAL>>>(pn2, pw1, fc1_b, nullptr, ph, 1024, 256, 1);
    tgemm_kernel<<<dim3(2, 512), 256, SMEM_TOTAL>>>(ph, pw2, fc2_b, px1, py, 256, 1024, 2);

    out_transpose<<<dim3(8, 512, 4), dim3(32, 8)>>>(out);
}

// round 6
// speedup vs baseline: 5.0227x; 1.3863x over previous
#include <cuda_runtime.h>
#include <cuda_bf16.h>
#include <math.h>
#include <stdint.h>

// ---------------------------------------------------------------------------
// TransformerBlock (3x3 neighborhood attention). bf16 mma.sync GEMMs
// (fp32 accum), fused QKV (N=768), cp.async 3-stage pipeline, BK=32.
// ---------------------------------------------------------------------------

#define N_TOK 65536
#define CCH   256
#define HIDN  1024
#define HW    16384
#define WD    128
#define EPSF  1e-5f

__device__ float          g_xc [(size_t)N_TOK * CCH];
__device__ __nv_bfloat16  g_n1 [(size_t)N_TOK * CCH];
__device__ float          g_qkv[(size_t)N_TOK * 768];
__device__ float          g_x1 [(size_t)N_TOK * CCH];
__device__ __nv_bfloat16  g_n2 [(size_t)N_TOK * CCH];
__device__ __nv_bfloat16  g_h  [(size_t)N_TOK * HIDN];
__device__ float          g_y  [(size_t)N_TOK * CCH];

// transposed bf16 weights wt[n][k]
__device__ __nv_bfloat16 g_wqkv_t[768 * CCH];          // q rows 0-255, k 256-511, v 512-767
__device__ __nv_bfloat16 g_w1_t[(size_t)HIDN * CCH];
__device__ __nv_bfloat16 g_w2_t[(size_t)CCH * HIDN];
__device__ float         g_bqkv[768];

// ---------------------------------------------------------------------------
// weight transpose + bf16 round: w[K][N] -> wt[N][K]
// ---------------------------------------------------------------------------
__global__ void wconv_kernel(const float* __restrict__ w, __nv_bfloat16* __restrict__ wt,
                             int K, int N)
{
    __shared__ float t[32][33];
    int tx = threadIdx.x, ty = threadIdx.y;    // (32,8)
    int n0 = blockIdx.x * 32, k0 = blockIdx.y * 32;
#pragma unroll
    for (int j = 0; j < 4; j++)
        t[ty + j * 8][tx] = w[(size_t)(k0 + ty + j * 8) * N + n0 + tx];
    __syncthreads();
#pragma unroll
    for (int j = 0; j < 4; j++)
        wt[(size_t)(n0 + ty + j * 8) * K + k0 + tx] = __float2bfloat16(t[tx][ty + j * 8]);
}

// ---------------------------------------------------------------------------
// LN1 + transpose [B,C,H,W] -> [N,C]; n1 stored bf16
// ---------------------------------------------------------------------------
__global__ __launch_bounds__(256) void ln1_kernel(const float* __restrict__ x,
                                                  const float* __restrict__ gam,
                                                  const float* __restrict__ bet)
{
    __shared__ float s[256][33];
    __shared__ float mu[32], rs[32];
    int tid = threadIdx.x;
    int tx = tid & 31, ty = tid >> 5;
    int blk = blockIdx.x;
    int b  = blk >> 9;
    int p0 = (blk & 511) << 5;

    const float* xb = x + ((size_t)b * CCH) * HW + p0 + tx;
#pragma unroll
    for (int i = 0; i < 32; i++) {
        int c = ty * 32 + i;
        s[c][tx] = xb[(size_t)c * HW];
    }
    __syncthreads();
    {
        int px = ty * 4 + (tx >> 3);
        int j  = tx & 7;
        float s1 = 0.f, s2 = 0.f;
#pragma unroll
        for (int m = 0; m < 32; m++) {
            float vv = s[j + 8 * m][px];
            s1 += vv; s2 += vv * vv;
        }
#pragma unroll
        for (int off = 4; off >= 1; off >>= 1) {
            s1 += __shfl_xor_sync(0xffffffffu, s1, off);
            s2 += __shfl_xor_sync(0xffffffffu, s2, off);
        }
        if (j == 0) {
            float m1  = s1 * (1.f / 256.f);
            float var = fmaxf(s2 * (1.f / 256.f) - m1 * m1, 0.f);
            mu[px] = m1;
            rs[px] = rsqrtf(var + EPSF);
        }
    }
    __syncthreads();

    float gr = gam[tid], br = bet[tid];
    size_t tbase = ((size_t)b * HW + p0) * CCH + tid;
#pragma unroll
    for (int j = 0; j < 32; j++) {
        float xv = s[tid][j];
        g_xc[tbase + (size_t)j * CCH] = xv;
        g_n1[tbase + (size_t)j * CCH] =
            __float2bfloat16((xv - mu[j]) * rs[j] * gr + br);
    }
}

// ---------------------------------------------------------------------------
// bf16 GEMM: C[M,N] = A[M,K] @ Bt[N,K]^T + bias (+epi), fp32 accum.
// 128x128 tile, BK=32, 8 warps (warp tile 64x32), 3-stage cp.async.
// Smem rows: 32 bf16 = 64B, chunk swizzle c ^= (row>>1)&3 (conflict-free).
// epi: 0 bias (fp32 out); 1 bias+GELU (bf16 out); 2 bias+residual (fp32 out).
// ---------------------------------------------------------------------------
#define TILE_BYTES 8192                    // 128 rows * 64 B
#define STAGE_BYTES (2 * TILE_BYTES)       // A + B
#define NSTAGE 3
#define SMEM_TOTAL (NSTAGE * STAGE_BYTES)  // 49152

__device__ __forceinline__ void cpasync16(uint32_t dst, const void* src) {
    asm volatile("cp.async.cg.shared.global [%0], [%1], 16;" :: "r"(dst), "l"(src));
}
__device__ __forceinline__ void ldsm4(uint32_t& r0, uint32_t& r1, uint32_t& r2,
                                      uint32_t& r3, uint32_t addr) {
    asm volatile("ldmatrix.sync.aligned.m8n8.x4.shared.b16 {%0,%1,%2,%3}, [%4];"
                 : "=r"(r0), "=r"(r1), "=r"(r2), "=r"(r3) : "r"(addr));
}
__device__ __forceinline__ void mma_bf16(float* c, const uint32_t* a, const uint32_t* b) {
    asm volatile(
        "mma.sync.aligned.m16n8k16.row.col.f32.bf16.bf16.f32 "
        "{%0,%1,%2,%3},{%4,%5,%6,%7},{%8,%9},{%0,%1,%2,%3};"
        : "+f"(c[0]), "+f"(c[1]), "+f"(c[2]), "+f"(c[3])
        : "r"(a[0]), "r"(a[1]), "r"(a[2]), "r"(a[3]), "r"(b[0]), "r"(b[1]));
}

__global__ __launch_bounds__(256) void bgemm_kernel(
    const __nv_bfloat16* __restrict__ A, const __nv_bfloat16* __restrict__ Bt,
    const float* __restrict__ bias, const float* __restrict__ res,
    void* __restrict__ Cv, int N, int K, int epi)
{
    extern __shared__ uint8_t smem[];
    int tid = threadIdx.x;
    int bx = blockIdx.x, by = blockIdx.y;
    int lane = tid & 31, warp = tid >> 5;
    int wm = warp >> 2, wn = warp & 3;

    const __nv_bfloat16* Ag  = A  + (size_t)by * 128 * K;
    const __nv_bfloat16* Btg = Bt + (size_t)bx * 128 * K;

    // cp.async: thread -> row r, chunk pair cp,cp+1 (16B chunks of 8 bf16)
    int r  = tid >> 1;
    int cp = (tid & 1) * 2;
    int wkey = (r >> 1) & 3;
    uint32_t sBase = (uint32_t)__cvta_generic_to_shared(smem);
    const __nv_bfloat16* Asrc = Ag  + (size_t)r * K + cp * 8;
    const __nv_bfloat16* Bsrc = Btg + (size_t)r * K + cp * 8;
    uint32_t dstA0 = sBase + r * 64 + ((cp    ) ^ wkey) * 16;
    uint32_t dstA1 = sBase + r * 64 + ((cp + 1) ^ wkey) * 16;

    // fragment addressing
    int fkey  = ((lane & 15) >> 1) & 3;
    int khalf = lane >> 4;                       // 0: k0-7 chunk, 1: k8-15 chunk
    uint32_t aRow = (uint32_t)(wm * 64 + (lane & 15)) * 64;
    uint32_t bRow = (uint32_t)TILE_BYTES + (uint32_t)(wn * 32 + (lane & 15)) * 64;

    float acc[4][4][4];
#pragma unroll
    for (int i = 0; i < 4; i++)
#pragma unroll
        for (int j = 0; j < 4; j++)
#pragma unroll
            for (int k = 0; k < 4; k++) acc[i][j][k] = 0.f;

    int niter = K >> 5;

    // prologue: stages 0,1
#pragma unroll
    for (int p = 0; p < 2; p++) {
        uint32_t sb = p * STAGE_BYTES;
        int k0 = p << 5;
        cpasync16(dstA0 + sb, Asrc + k0);
        cpasync16(dstA1 + sb, Asrc + k0 + 8);
        cpasync16(dstA0 + sb + TILE_BYTES, Bsrc + k0);
        cpasync16(dstA1 + sb + TILE_BYTES, Bsrc + k0 + 8);
        asm volatile("cp.async.commit_group;");
    }

    int st = 0;
    for (int it = 0; it < niter; ++it) {
        int pre = it + 2;
        if (pre < niter) {
            int ps = pre % NSTAGE;
            uint32_t sb = ps * STAGE_BYTES;
            int k0 = pre << 5;
            cpasync16(dstA0 + sb, Asrc + k0);
            cpasync16(dstA1 + sb, Asrc + k0 + 8);
            cpasync16(dstA0 + sb + TILE_BYTES, Bsrc + k0);
            cpasync16(dstA1 + sb + TILE_BYTES, Bsrc + k0 + 8);
        }
        asm volatile("cp.async.commit_group;");
        asm volatile("cp.async.wait_group 2;" ::: "memory");
        __syncthreads();

        uint32_t stb = st * STAGE_BYTES;
#pragma unroll
        for (int s = 0; s < 2; s++) {           // two k16 steps per BK=32
            int chunk = s * 2 + khalf;
            uint32_t aoff = sBase + stb + aRow + ((chunk ^ fkey) * 16);
            uint32_t boff = sBase + stb + bRow + ((chunk ^ fkey) * 16);
            uint32_t a[4][4], b[4][2];
#pragma unroll
            for (int mi = 0; mi < 4; mi++)
                ldsm4(a[mi][0], a[mi][1], a[mi][2], a[mi][3], aoff + mi * 1024);
#pragma unroll
            for (int h = 0; h < 2; h++) {
                uint32_t q0, q1, q2, q3;
                ldsm4(q0, q1, q2, q3, boff + h * 1024);
                b[h * 2][0]     = q0; b[h * 2][1]     = q2;
                b[h * 2 + 1][0] = q1; b[h * 2 + 1][1] = q3;
            }
#pragma unroll
            for (int mi = 0; mi < 4; mi++)
#pragma unroll
                for (int ni = 0; ni < 4; ni++)
                    mma_bf16(acc[mi][ni], a[mi], b[ni]);
        }
        __syncthreads();
        st = (st + 1) % NSTAGE;
    }

    // epilogue
    int colBase = bx * 128 + wn * 32;
    int rowBase = by * 128 + wm * 64 + (lane >> 2);
    float* C = (float*)Cv;
    __nv_bfloat16* Cb = (__nv_bfloat16*)Cv;
#pragma unroll
    for (int ni = 0; ni < 4; ni++) {
        int c = colBase + ni * 8 + (lane & 3) * 2;
        float bi0 = bias[c], bi1 = bias[c + 1];
#pragma unroll
        for (int mi = 0; mi < 4; mi++) {
            int rr = rowBase + mi * 16;
            float v00 = acc[mi][ni][0] + bi0;
            float v01 = acc[mi][ni][1] + bi1;
            float v10 = acc[mi][ni][2] + bi0;
            float v11 = acc[mi][ni][3] + bi1;
            if (epi == 1) {
                v00 = 0.5f * v00 * (1.f + erff(v00 * 0.70710678118654752f));
                v01 = 0.5f * v01 * (1.f + erff(v01 * 0.70710678118654752f));
                v10 = 0.5f * v10 * (1.f + erff(v10 * 0.70710678118654752f));
                v11 = 0.5f * v11 * (1.f + erff(v11 * 0.70710678118654752f));
                *(__nv_bfloat162*)(Cb + (size_t)rr * N + c) =
                    __floats2bfloat162_rn(v00, v01);
                *(__nv_bfloat162*)(Cb + (size_t)(rr + 8) * N + c) =
                    __floats2bfloat162_rn(v10, v11);
            } else {
                if (epi == 2) {
                    float2 r0 = *(const float2*)(res + (size_t)rr * N + c);
                    float2 r1 = *(const float2*)(res + (size_t)(rr + 8) * N + c);
                    v00 += r0.x; v01 += r0.y; v10 += r1.x; v11 += r1.y;
                }
                *(float2*)(C + (size_t)rr * N + c) = make_float2(v00, v01);
                *(float2*)(C + (size_t)(rr + 8) * N + c) = make_float2(v10, v11);
            }
        }
    }
}

// ---------------------------------------------------------------------------
// 3x3 neighborhood attention + residual + fused LN2; q/k/v packed [N,768]
// ---------------------------------------------------------------------------
__global__ __launch_bounds__(256) void attn_kernel(const float* __restrict__ g2,
                                                   const float* __restrict__ b2)
{
    int lane = threadIdx.x & 31;
    int warp = threadIdx.x >> 5;
    int t = blockIdx.x * 8 + warp;
    int p = t & (HW - 1);
    int yy = p >> 7, xx = p & 127;
    size_t base  = (size_t)t * CCH + lane;
    size_t qbase = (size_t)t * 768 + lane;

    float ql[8];
#pragma unroll
    for (int i = 0; i < 8; i++) ql[i] = g_qkv[qbase + 32 * i];

    float sc[9];
    int tns[9];
    unsigned vmask = 0;
#pragma unroll
    for (int n = 0; n < 9; n++) {
        int dy = n / 3 - 1, dx = n % 3 - 1;
        int ny = yy + dy, nx = xx + dx;
        bool valid = ((unsigned)ny < 128u) && ((unsigned)nx < 128u);
        int tn = t + dy * WD + dx;
        tns[n] = tn;
        if (valid) {
            vmask |= 1u << n;
            const float* kp = g_qkv + (size_t)tn * 768 + 256 + lane;
            float dot = 0.f;
#pragma unroll
            for (int i = 0; i < 8; i++) dot += ql[i] * kp[32 * i];
#pragma unroll
            for (int off = 16; off >= 1; off >>= 1)
                dot += __shfl_xor_sync(0xffffffffu, dot, off);
            sc[n] = dot * (1.0f / 16.0f);
        } else {
            sc[n] = -1e30f;
        }
    }

    float mx = sc[0];
#pragma unroll
    for (int n = 1; n < 9; n++) mx = fmaxf(mx, sc[n]);
    float w[9], wsum = 0.f;
#pragma unroll
    for (int n = 0; n < 9; n++) {
        w[n] = ((vmask >> n) & 1u) ? expf(sc[n] - mx) : 0.f;
        wsum += w[n];
    }
    float inv = 1.f / wsum;

    float acc[8];
#pragma unroll
    for (int i = 0; i < 8; i++) acc[i] = 0.f;
#pragma unroll
    for (int n = 0; n < 9; n++) {
        if ((vmask >> n) & 1u) {
            float wn = w[n] * inv;
            const float* vp = g_qkv + (size_t)tns[n] * 768 + 512 + lane;
#pragma unroll
            for (int i = 0; i < 8; i++) acc[i] += wn * vp[32 * i];
        }
    }

    float xv[8], s1 = 0.f, s2 = 0.f;
#pragma unroll
    for (int i = 0; i < 8; i++) {
        float val = g_xc[base + 32 * i] + acc[i];
        xv[i] = val; s1 += val; s2 += val * val;
    }
#pragma unroll
    for (int off = 16; off >= 1; off >>= 1) {
        s1 += __shfl_xor_sync(0xffffffffu, s1, off);
        s2 += __shfl_xor_sync(0xffffffffu, s2, off);
    }
    float m1  = s1 * (1.f / 256.f);
    float var = fmaxf(s2 * (1.f / 256.f) - m1 * m1, 0.f);
    float rstd = rsqrtf(var + EPSF);
#pragma unroll
    for (int i = 0; i < 8; i++) {
        int c = lane + 32 * i;
        g_x1[base + 32 * i] = xv[i];
        g_n2[base + 32 * i] =
            __float2bfloat16((xv[i] - m1) * rstd * g2[c] + b2[c]);
    }
}

// ---------------------------------------------------------------------------
// transpose [N,C] -> [B,C,H,W]
// ---------------------------------------------------------------------------
__global__ void out_transpose(float* __restrict__ out)
{
    __shared__ float tile[32][33];
    int tx = threadIdx.x, ty = threadIdx.y;
    int c0 = blockIdx.x * 32;
    int p0 = blockIdx.y * 32;
    int b  = blockIdx.z;

    size_t ybase = ((size_t)b * HW + p0) * CCH + c0;
#pragma unroll
    for (int j = 0; j < 4; j++) {
        int tok = ty + j * 8;
        tile[tok][tx] = g_y[ybase + (size_t)tok * CCH + tx];
    }
    __syncthreads();
    size_t obase = ((size_t)b * CCH + c0) * HW + p0;
#pragma unroll
    for (int j = 0; j < 4; j++) {
        int c = ty + j * 8;
        out[obase + (size_t)c * HW + tx] = tile[tx][c];
    }
}

// ---------------------------------------------------------------------------
extern "C" void kernel_launch(void* const* d_in, const int* in_sizes, int n_in,
                              void* d_out, int out_size)
{
    (void)in_sizes; (void)n_in; (void)out_size;
    const float* x     = (const float*)d_in[0];
    const float* wq    = (const float*)d_in[1];
    const float* bq    = (const float*)d_in[2];
    const float* wk    = (const float*)d_in[3];
    const float* bk    = (const float*)d_in[4];
    const float* wv    = (const float*)d_in[5];
    const float* bv    = (const float*)d_in[6];
    const float* ln1_g = (const float*)d_in[7];
    const float* ln1_b = (const float*)d_in[8];
    const float* ln2_g = (const float*)d_in[9];
    const float* ln2_b = (const float*)d_in[10];
    const float* fc1_w = (const float*)d_in[11];
    const float* fc1_b = (const float*)d_in[12];
    const float* fc2_w = (const float*)d_in[13];
    const float* fc2_b = (const float*)d_in[14];
    float* out = (float*)d_out;

    __nv_bfloat16 *pn1, *pn2, *ph, *pwqkv, *pw1, *pw2;
    float *pqkv, *px1, *py, *pxc, *pbqkv;
    cudaGetSymbolAddress((void**)&pn1,   g_n1);
    cudaGetSymbolAddress((void**)&pn2,   g_n2);
    cudaGetSymbolAddress((void**)&ph,    g_h);
    cudaGetSymbolAddress((void**)&pwqkv, g_wqkv_t);
    cudaGetSymbolAddress((void**)&pw1,   g_w1_t);
    cudaGetSymbolAddress((void**)&pw2,   g_w2_t);
    cudaGetSymbolAddress((void**)&pqkv,  g_qkv);
    cudaGetSymbolAddress((void**)&px1,   g_x1);
    cudaGetSymbolAddress((void**)&py,    g_y);
    cudaGetSymbolAddress((void**)&pxc,   g_xc);
    cudaGetSymbolAddress((void**)&pbqkv, g_bqkv);

    cudaFuncSetAttribute(bgemm_kernel,
                         cudaFuncAttributeMaxDynamicSharedMemorySize, SMEM_TOTAL);

    // fused QKV bias
    cudaMemcpyAsync(pbqkv,       bq, 256 * sizeof(float), cudaMemcpyDeviceToDevice);
    cudaMemcpyAsync(pbqkv + 256, bk, 256 * sizeof(float), cudaMemcpyDeviceToDevice);
    cudaMemcpyAsync(pbqkv + 512, bv, 256 * sizeof(float), cudaMemcpyDeviceToDevice);

    dim3 tb(32, 8);
    wconv_kernel<<<dim3(8, 8),  tb>>>(wq,    pwqkv,             256, 256);
    wconv_kernel<<<dim3(8, 8),  tb>>>(wk,    pwqkv + 256 * 256, 256, 256);
    wconv_kernel<<<dim3(8, 8),  tb>>>(wv,    pwqkv + 512 * 256, 256, 256);
    wconv_kernel<<<dim3(32, 8), tb>>>(fc1_w, pw1, 256, 1024);
    wconv_kernel<<<dim3(8, 32), tb>>>(fc2_w, pw2, 1024, 256);

    ln1_kernel<<<2048, 256>>>(x, ln1_g, ln1_b);

    // fused QKV: M=65536, N=768, K=256
    bgemm_kernel<<<dim3(6, 512), 256, SMEM_TOTAL>>>(pn1, pwqkv, pbqkv, nullptr,
                                                    pqkv, 768, 256, 0);

    attn_kernel<<<8192, 256>>>(ln2_g, ln2_b);

    // fc1 + GELU -> bf16 h
    bgemm_kernel<<<dim3(8, 512), 256, SMEM_TOTAL>>>(pn2, pw1, fc1_b, nullptr,
                                                    ph, 1024, 256, 1);
    // fc2 + bias + residual -> y
    bgemm_kernel<<<dim3(2, 512), 256, SMEM_TOTAL>>>(ph, pw2, fc2_b, px1,
                                                    py, 256, 1024, 2);

    out_transpose<<<dim3(8, 512, 4), dim3(32, 8)>>>(out);
}

// round 7
// speedup vs baseline: 5.2224x; 1.0398x over previous
#include <cuda_runtime.h>
#include <cuda_bf16.h>
#include <math.h>
#include <stdint.h>

// ---------------------------------------------------------------------------
// TransformerBlock (3x3 neighborhood attention). bf16 mma.sync GEMMs
// (fp32 accum), fused QKV (N=768, bf16 out), bf16 attention operands,
// fc2 epilogue writes transposed [B,C,H,W] output directly.
// ---------------------------------------------------------------------------

#define N_TOK 65536
#define CCH   256
#define HIDN  1024
#define HW    16384
#define WD    128
#define EPSF  1e-5f

__device__ float          g_xc [(size_t)N_TOK * CCH];
__device__ __nv_bfloat16  g_n1 [(size_t)N_TOK * CCH];
__device__ __nv_bfloat16  g_qkv[(size_t)N_TOK * 768];
__device__ float          g_x1 [(size_t)N_TOK * CCH];
__device__ __nv_bfloat16  g_n2 [(size_t)N_TOK * CCH];
__device__ __nv_bfloat16  g_h  [(size_t)N_TOK * HIDN];

// transposed bf16 weights wt[n][k]
__device__ __nv_bfloat16 g_wqkv_t[768 * CCH];   // q 0-255, k 256-511, v 512-767
__device__ __nv_bfloat16 g_w1_t[(size_t)HIDN * CCH];
__device__ __nv_bfloat16 g_w2_t[(size_t)CCH * HIDN];
__device__ float         g_bqkv[768];

// ---------------------------------------------------------------------------
// weight transpose + bf16 round: w[K][N] -> wt[N][K]
// ---------------------------------------------------------------------------
__global__ void wconv_kernel(const float* __restrict__ w, __nv_bfloat16* __restrict__ wt,
                             int K, int N)
{
    __shared__ float t[32][33];
    int tx = threadIdx.x, ty = threadIdx.y;    // (32,8)
    int n0 = blockIdx.x * 32, k0 = blockIdx.y * 32;
#pragma unroll
    for (int j = 0; j < 4; j++)
        t[ty + j * 8][tx] = w[(size_t)(k0 + ty + j * 8) * N + n0 + tx];
    __syncthreads();
#pragma unroll
    for (int j = 0; j < 4; j++)
        wt[(size_t)(n0 + ty + j * 8) * K + k0 + tx] = __float2bfloat16(t[tx][ty + j * 8]);
}

// ---------------------------------------------------------------------------
// LN1 + transpose [B,C,H,W] -> [N,C]; n1 stored bf16
// ---------------------------------------------------------------------------
__global__ __launch_bounds__(256) void ln1_kernel(const float* __restrict__ x,
                                                  const float* __restrict__ gam,
                                                  const float* __restrict__ bet)
{
    __shared__ float s[256][33];
    __shared__ float mu[32], rs[32];
    int tid = threadIdx.x;
    int tx = tid & 31, ty = tid >> 5;
    int blk = blockIdx.x;
    int b  = blk >> 9;
    int p0 = (blk & 511) << 5;

    const float* xb = x + ((size_t)b * CCH) * HW + p0 + tx;
#pragma unroll
    for (int i = 0; i < 32; i++) {
        int c = ty * 32 + i;
        s[c][tx] = xb[(size_t)c * HW];
    }
    __syncthreads();
    {
        int px = ty * 4 + (tx >> 3);
        int j  = tx & 7;
        float s1 = 0.f, s2 = 0.f;
#pragma unroll
        for (int m = 0; m < 32; m++) {
            float vv = s[j + 8 * m][px];
            s1 += vv; s2 += vv * vv;
        }
#pragma unroll
        for (int off = 4; off >= 1; off >>= 1) {
            s1 += __shfl_xor_sync(0xffffffffu, s1, off);
            s2 += __shfl_xor_sync(0xffffffffu, s2, off);
        }
        if (j == 0) {
            float m1  = s1 * (1.f / 256.f);
            float var = fmaxf(s2 * (1.f / 256.f) - m1 * m1, 0.f);
            mu[px] = m1;
            rs[px] = rsqrtf(var + EPSF);
        }
    }
    __syncthreads();

    float gr = gam[tid], br = bet[tid];
    size_t tbase = ((size_t)b * HW + p0) * CCH + tid;
#pragma unroll
    for (int j = 0; j < 32; j++) {
        float xv = s[tid][j];
        g_xc[tbase + (size_t)j * CCH] = xv;
        g_n1[tbase + (size_t)j * CCH] =
            __float2bfloat16((xv - mu[j]) * rs[j] * gr + br);
    }
}

// ---------------------------------------------------------------------------
// bf16 GEMM: C[M,N] = A[M,K] @ Bt[N,K]^T + bias (+epi), fp32 accum.
// 128x128 tile, BK=32, 8 warps (warp tile 64x32), 3-stage cp.async.
// epi: 0 bias (bf16 out); 1 bias+GELU (bf16 out);
//      2 bias+residual -> transposed fp32 [B,C,H,W] write (N must be 256).
// ---------------------------------------------------------------------------
#define TILE_BYTES 8192                    // 128 rows * 64 B
#define STAGE_BYTES (2 * TILE_BYTES)       // A + B
#define NSTAGE 3
#define SMEM_TOTAL (NSTAGE * STAGE_BYTES)  // 49152

__device__ __forceinline__ void cpasync16(uint32_t dst, const void* src) {
    asm volatile("cp.async.cg.shared.global [%0], [%1], 16;" :: "r"(dst), "l"(src));
}
__device__ __forceinline__ void ldsm4(uint32_t& r0, uint32_t& r1, uint32_t& r2,
                                      uint32_t& r3, uint32_t addr) {
    asm volatile("ldmatrix.sync.aligned.m8n8.x4.shared.b16 {%0,%1,%2,%3}, [%4];"
                 : "=r"(r0), "=r"(r1), "=r"(r2), "=r"(r3) : "r"(addr));
}
__device__ __forceinline__ void mma_bf16(float* c, const uint32_t* a, const uint32_t* b) {
    asm volatile(
        "mma.sync.aligned.m16n8k16.row.col.f32.bf16.bf16.f32 "
        "{%0,%1,%2,%3},{%4,%5,%6,%7},{%8,%9},{%0,%1,%2,%3};"
        : "+f"(c[0]), "+f"(c[1]), "+f"(c[2]), "+f"(c[3])
        : "r"(a[0]), "r"(a[1]), "r"(a[2]), "r"(a[3]), "r"(b[0]), "r"(b[1]));
}

__global__ __launch_bounds__(256) void bgemm_kernel(
    const __nv_bfloat16* __restrict__ A, const __nv_bfloat16* __restrict__ Bt,
    const float* __restrict__ bias, const float* __restrict__ res,
    void* __restrict__ Cv, int N, int K, int epi)
{
    extern __shared__ uint8_t smem[];
    int tid = threadIdx.x;
    int bx = blockIdx.x, by = blockIdx.y;
    int lane = tid & 31, warp = tid >> 5;
    int wm = warp >> 2, wn = warp & 3;

    const __nv_bfloat16* Ag  = A  + (size_t)by * 128 * K;
    const __nv_bfloat16* Btg = Bt + (size_t)bx * 128 * K;

    // cp.async: thread -> row r, chunk pair cp,cp+1 (16B chunks of 8 bf16)
    int r  = tid >> 1;
    int cp = (tid & 1) * 2;
    int wkey = (r >> 1) & 3;
    uint32_t sBase = (uint32_t)__cvta_generic_to_shared(smem);
    const __nv_bfloat16* Asrc = Ag  + (size_t)r * K + cp * 8;
    const __nv_bfloat16* Bsrc = Btg + (size_t)r * K + cp * 8;
    uint32_t dstA0 = sBase + r * 64 + ((cp    ) ^ wkey) * 16;
    uint32_t dstA1 = sBase + r * 64 + ((cp + 1) ^ wkey) * 16;

    // fragment addressing
    int fkey  = ((lane & 15) >> 1) & 3;
    int khalf = lane >> 4;
    uint32_t aRow = (uint32_t)(wm * 64 + (lane & 15)) * 64;
    uint32_t bRow = (uint32_t)TILE_BYTES + (uint32_t)(wn * 32 + (lane & 15)) * 64;

    float acc[4][4][4];
#pragma unroll
    for (int i = 0; i < 4; i++)
#pragma unroll
        for (int j = 0; j < 4; j++)
#pragma unroll
            for (int k = 0; k < 4; k++) acc[i][j][k] = 0.f;

    int niter = K >> 5;

#pragma unroll
    for (int p = 0; p < 2; p++) {
        uint32_t sb = p * STAGE_BYTES;
        int k0 = p << 5;
        cpasync16(dstA0 + sb, Asrc + k0);
        cpasync16(dstA1 + sb, Asrc + k0 + 8);
        cpasync16(dstA0 + sb + TILE_BYTES, Bsrc + k0);
        cpasync16(dstA1 + sb + TILE_BYTES, Bsrc + k0 + 8);
        asm volatile("cp.async.commit_group;");
    }

    int st = 0;
    for (int it = 0; it < niter; ++it) {
        int pre = it + 2;
        if (pre < niter) {
            int ps = pre % NSTAGE;
            uint32_t sb = ps * STAGE_BYTES;
            int k0 = pre << 5;
            cpasync16(dstA0 + sb, Asrc + k0);
            cpasync16(dstA1 + sb, Asrc + k0 + 8);
            cpasync16(dstA0 + sb + TILE_BYTES, Bsrc + k0);
            cpasync16(dstA1 + sb + TILE_BYTES, Bsrc + k0 + 8);
        }
        asm volatile("cp.async.commit_group;");
        asm volatile("cp.async.wait_group 2;" ::: "memory");
        __syncthreads();

        uint32_t stb = st * STAGE_BYTES;
#pragma unroll
        for (int s = 0; s < 2; s++) {
            int chunk = s * 2 + khalf;
            uint32_t aoff = sBase + stb + aRow + ((chunk ^ fkey) * 16);
            uint32_t boff = sBase + stb + bRow + ((chunk ^ fkey) * 16);
            uint32_t a[4][4], b[4][2];
#pragma unroll
            for (int mi = 0; mi < 4; mi++)
                ldsm4(a[mi][0], a[mi][1], a[mi][2], a[mi][3], aoff + mi * 1024);
#pragma unroll
            for (int h = 0; h < 2; h++) {
                uint32_t q0, q1, q2, q3;
                ldsm4(q0, q1, q2, q3, boff + h * 1024);
                b[h * 2][0]     = q0; b[h * 2][1]     = q2;
                b[h * 2 + 1][0] = q1; b[h * 2 + 1][1] = q3;
            }
#pragma unroll
            for (int mi = 0; mi < 4; mi++)
#pragma unroll
                for (int ni = 0; ni < 4; ni++)
                    mma_bf16(acc[mi][ni], a[mi], b[ni]);
        }
        __syncthreads();
        st = (st + 1) % NSTAGE;
    }

    if (epi == 2) {
        // bias + residual, then transpose through smem and write [B,C,H,W].
        float* smf = (float*)smem;              // [64][132] fp32 = 33792 B
        float* outp = (float*)Cv;
        int t0 = by * 128;
        int b  = t0 >> 14;
        int p0 = t0 & (HW - 1);
        int c0 = bx * 128;
#pragma unroll
        for (int h = 0; h < 2; h++) {
            __syncthreads();
#pragma unroll
            for (int ni = 0; ni < 4; ni++) {
                int cl = wn * 32 + ni * 8 + (lane & 3) * 2;   // 0..127
                if ((cl >> 6) != h) continue;
                int cg = c0 + cl;
                float bi0 = bias[cg], bi1 = bias[cg + 1];
                int cc = cl & 63;
#pragma unroll
                for (int mi = 0; mi < 4; mi++) {
                    int rl = wm * 64 + mi * 16 + (lane >> 2); // 0..127 (and +8)
                    size_t rg = (size_t)(t0 + rl);
                    float2 r0 = *(const float2*)(res + rg * 256 + cg);
                    float2 r1 = *(const float2*)(res + (rg + 8) * 256 + cg);
                    smf[cc * 132 + rl]           = acc[mi][ni][0] + bi0 + r0.x;
                    smf[(cc + 1) * 132 + rl]     = acc[mi][ni][1] + bi1 + r0.y;
                    smf[cc * 132 + rl + 8]       = acc[mi][ni][2] + bi0 + r1.x;
                    smf[(cc + 1) * 132 + rl + 8] = acc[mi][ni][3] + bi1 + r1.y;
                }
            }
            __syncthreads();
            int ch = tid >> 2, seg = tid & 3;
            float* op = outp + ((size_t)b * CCH + c0 + h * 64 + ch) * HW + p0;
            const float* sp = smf + ch * 132;
#pragma unroll
            for (int j = 0; j < 8; j++) {
                int idx = seg + 4 * j;       // float4 index within 128-float row
                ((float4*)op)[idx] = ((const float4*)sp)[idx];
            }
        }
        return;
    }

    // epi 0/1: bf16 output
    int colBase = bx * 128 + wn * 32;
    int rowBase = by * 128 + wm * 64 + (lane >> 2);
    __nv_bfloat16* Cb = (__nv_bfloat16*)Cv;
#pragma unroll
    for (int ni = 0; ni < 4; ni++) {
        int c = colBase + ni * 8 + (lane & 3) * 2;
        float bi0 = bias[c], bi1 = bias[c + 1];
#pragma unroll
        for (int mi = 0; mi < 4; mi++) {
            int rr = rowBase + mi * 16;
            float v00 = acc[mi][ni][0] + bi0;
            float v01 = acc[mi][ni][1] + bi1;
            float v10 = acc[mi][ni][2] + bi0;
            float v11 = acc[mi][ni][3] + bi1;
            if (epi == 1) {
                v00 = 0.5f * v00 * (1.f + erff(v00 * 0.70710678118654752f));
                v01 = 0.5f * v01 * (1.f + erff(v01 * 0.70710678118654752f));
                v10 = 0.5f * v10 * (1.f + erff(v10 * 0.70710678118654752f));
                v11 = 0.5f * v11 * (1.f + erff(v11 * 0.70710678118654752f));
            }
            *(__nv_bfloat162*)(Cb + (size_t)rr * N + c) =
                __floats2bfloat162_rn(v00, v01);
            *(__nv_bfloat162*)(Cb + (size_t)(rr + 8) * N + c) =
                __floats2bfloat162_rn(v10, v11);
        }
    }
}

// ---------------------------------------------------------------------------
// 3x3 neighborhood attention + residual + fused LN2; q/k/v bf16 packed [N,768]
// ---------------------------------------------------------------------------
__global__ __launch_bounds__(256) void attn_kernel(const float* __restrict__ g2,
                                                   const float* __restrict__ b2)
{
    int lane = threadIdx.x & 31;
    int warp = threadIdx.x >> 5;
    int t = blockIdx.x * 8 + warp;
    int p = t & (HW - 1);
    int yy = p >> 7, xx = p & 127;

    const __nv_bfloat162* qp = (const __nv_bfloat162*)(g_qkv + (size_t)t * 768) + lane;
    float2 ql[4];
#pragma unroll
    for (int i = 0; i < 4; i++) ql[i] = __bfloat1622float2(qp[32 * i]);

    float sc[9];
    int tns[9];
    unsigned vmask = 0;
#pragma unroll
    for (int n = 0; n < 9; n++) {
        int dy = n / 3 - 1, dx = n % 3 - 1;
        int ny = yy + dy, nx = xx + dx;
        bool valid = ((unsigned)ny < 128u) && ((unsigned)nx < 128u);
        int tn = t + dy * WD + dx;
        tns[n] = tn;
        if (valid) {
            vmask |= 1u << n;
            const __nv_bfloat162* kp =
                (const __nv_bfloat162*)(g_qkv + (size_t)tn * 768 + 256) + lane;
            float dot = 0.f;
#pragma unroll
            for (int i = 0; i < 4; i++) {
                float2 kv = __bfloat1622float2(kp[32 * i]);
                dot += ql[i].x * kv.x + ql[i].y * kv.y;
            }
#pragma unroll
            for (int off = 16; off >= 1; off >>= 1)
                dot += __shfl_xor_sync(0xffffffffu, dot, off);
            sc[n] = dot * (1.0f / 16.0f);
        } else {
            sc[n] = -1e30f;
        }
    }

    float mx = sc[0];
#pragma unroll
    for (int n = 1; n < 9; n++) mx = fmaxf(mx, sc[n]);
    float w[9], wsum = 0.f;
#pragma unroll
    for (int n = 0; n < 9; n++) {
        w[n] = ((vmask >> n) & 1u) ? expf(sc[n] - mx) : 0.f;
        wsum += w[n];
    }
    float inv = 1.f / wsum;

    float2 acc[4];
#pragma unroll
    for (int i = 0; i < 4; i++) acc[i] = make_float2(0.f, 0.f);
#pragma unroll
    for (int n = 0; n < 9; n++) {
        if ((vmask >> n) & 1u) {
            float wn = w[n] * inv;
            const __nv_bfloat162* vp =
                (const __nv_bfloat162*)(g_qkv + (size_t)tns[n] * 768 + 512) + lane;
#pragma unroll
            for (int i = 0; i < 4; i++) {
                float2 vv = __bfloat1622float2(vp[32 * i]);
                acc[i].x += wn * vv.x;
                acc[i].y += wn * vv.y;
            }
        }
    }

    const float2* xp = (const float2*)(g_xc + (size_t)t * CCH) + lane;
    float2 xv[4];
    float s1 = 0.f, s2 = 0.f;
#pragma unroll
    for (int i = 0; i < 4; i++) {
        float2 xr = xp[32 * i];
        xv[i].x = xr.x + acc[i].x;
        xv[i].y = xr.y + acc[i].y;
        s1 += xv[i].x + xv[i].y;
        s2 += xv[i].x * xv[i].x + xv[i].y * xv[i].y;
    }
#pragma unroll
    for (int off = 16; off >= 1; off >>= 1) {
        s1 += __shfl_xor_sync(0xffffffffu, s1, off);
        s2 += __shfl_xor_sync(0xffffffffu, s2, off);
    }
    float m1  = s1 * (1.f / 256.f);
    float var = fmaxf(s2 * (1.f / 256.f) - m1 * m1, 0.f);
    float rstd = rsqrtf(var + EPSF);

    float2* x1p = (float2*)(g_x1 + (size_t)t * CCH) + lane;
    __nv_bfloat162* n2p = (__nv_bfloat162*)(g_n2 + (size_t)t * CCH) + lane;
    const float2* g2p = (const float2*)g2 + lane;
    const float2* b2p = (const float2*)b2 + lane;
#pragma unroll
    for (int i = 0; i < 4; i++) {
        float2 gg = g2p[32 * i], bb = b2p[32 * i];
        x1p[32 * i] = xv[i];
        n2p[32 * i] = __floats2bfloat162_rn(
            (xv[i].x - m1) * rstd * gg.x + bb.x,
            (xv[i].y - m1) * rstd * gg.y + bb.y);
    }
}

// ---------------------------------------------------------------------------
extern "C" void kernel_launch(void* const* d_in, const int* in_sizes, int n_in,
                              void* d_out, int out_size)
{
    (void)in_sizes; (void)n_in; (void)out_size;
    const float* x     = (const float*)d_in[0];
    const float* wq    = (const float*)d_in[1];
    const float* bq    = (const float*)d_in[2];
    const float* wk    = (const float*)d_in[3];
    const float* bk    = (const float*)d_in[4];
    const float* wv    = (const float*)d_in[5];
    const float* bv    = (const float*)d_in[6];
    const float* ln1_g = (const float*)d_in[7];
    const float* ln1_b = (const float*)d_in[8];
    const float* ln2_g = (const float*)d_in[9];
    const float* ln2_b = (const float*)d_in[10];
    const float* fc1_w = (const float*)d_in[11];
    const float* fc1_b = (const float*)d_in[12];
    const float* fc2_w = (const float*)d_in[13];
    const float* fc2_b = (const float*)d_in[14];
    float* out = (float*)d_out;

    __nv_bfloat16 *pn1, *pn2, *ph, *pwqkv, *pw1, *pw2, *pqkv;
    float *px1, *pbqkv;
    cudaGetSymbolAddress((void**)&pn1,   g_n1);
    cudaGetSymbolAddress((void**)&pn2,   g_n2);
    cudaGetSymbolAddress((void**)&ph,    g_h);
    cudaGetSymbolAddress((void**)&pwqkv, g_wqkv_t);
    cudaGetSymbolAddress((void**)&pw1,   g_w1_t);
    cudaGetSymbolAddress((void**)&pw2,   g_w2_t);
    cudaGetSymbolAddress((void**)&pqkv,  g_qkv);
    cudaGetSymbolAddress((void**)&px1,   g_x1);
    cudaGetSymbolAddress((void**)&pbqkv, g_bqkv);

    cudaFuncSetAttribute(bgemm_kernel,
                         cudaFuncAttributeMaxDynamicSharedMemorySize, SMEM_TOTAL);

    cudaMemcpyAsync(pbqkv,       bq, 256 * sizeof(float), cudaMemcpyDeviceToDevice);
    cudaMemcpyAsync(pbqkv + 256, bk, 256 * sizeof(float), cudaMemcpyDeviceToDevice);
    cudaMemcpyAsync(pbqkv + 512, bv, 256 * sizeof(float), cudaMemcpyDeviceToDevice);

    dim3 tb(32, 8);
    wconv_kernel<<<dim3(8, 8),  tb>>>(wq,    pwqkv,             256, 256);
    wconv_kernel<<<dim3(8, 8),  tb>>>(wk,    pwqkv + 256 * 256, 256, 256);
    wconv_kernel<<<dim3(8, 8),  tb>>>(wv,    pwqkv + 512 * 256, 256, 256);
    wconv_kernel<<<dim3(32, 8), tb>>>(fc1_w, pw1, 256, 1024);
    wconv_kernel<<<dim3(8, 32), tb>>>(fc2_w, pw2, 1024, 256);

    ln1_kernel<<<2048, 256>>>(x, ln1_g, ln1_b);

    // fused QKV: M=65536, N=768, K=256 -> bf16
    bgemm_kernel<<<dim3(6, 512), 256, SMEM_TOTAL>>>(pn1, pwqkv, pbqkv, nullptr,
                                                    pqkv, 768, 256, 0);

    attn_kernel<<<8192, 256>>>(ln2_g, ln2_b);

    // fc1 + GELU -> bf16 h
    bgemm_kernel<<<dim3(8, 512), 256, SMEM_TOTAL>>>(pn2, pw1, fc1_b, nullptr,
                                                    ph, 1024, 256, 1);
    // fc2 + bias + residual -> transposed fp32 out
    bgemm_kernel<<<dim3(2, 512), 256, SMEM_TOTAL>>>(ph, pw2, fc2_b, px1,
                                                    out, 256, 1024, 2);
}